// round 15
// baseline (speedup 1.0000x reference)
#include <cuda_runtime.h>
#include <cuda_fp16.h>
#include <cstdint>
#include <cstddef>

// ---------------------------------------------------------------------------
// Geometry
// ---------------------------------------------------------------------------
static constexpr int KF = 4096;
static constexpr int NF = 14336;
static constexpr int MROWS = 256;         // batch rows
static constexpr int NTILE = 128;
static constexpr int NCTA = NF / NTILE;   // 112
static constexpr int KC = 64;             // k per stage
static constexpr int NITER = KF / KC;     // 64

// x in MMA A-fragment layout: [chunk][mtile(16)][ks(4)][lane(32)][reg(4)] u32.
// 64*16*4*32*4 = 524288 u32 = 2MB (L2-resident).
__device__ __align__(16) uint32_t g_xa[64 * 16 * 4 * 32 * 4];

// SMEM: B fp16 tiles only, 2 stages x 16384 = 32KB.
static constexpr uint32_t SM_TOTAL = 32768;

// ---------------------------------------------------------------------------
// Helpers
// ---------------------------------------------------------------------------
__device__ __forceinline__ __half2 u2h(uint32_t u) { return *reinterpret_cast<__half2*>(&u); }
__device__ __forceinline__ uint32_t h2u(__half2 h) { return *reinterpret_cast<uint32_t*>(&h); }

__device__ __forceinline__ void ldsm_x4_t(uint32_t& r0, uint32_t& r1, uint32_t& r2, uint32_t& r3,
                                          uint32_t addr) {
    asm volatile("ldmatrix.sync.aligned.m8n8.x4.trans.shared.b16 {%0,%1,%2,%3}, [%4];"
                 : "=r"(r0), "=r"(r1), "=r"(r2), "=r"(r3) : "r"(addr));
}
__device__ __forceinline__ void mma16816(float (&d)[4], const uint32_t* a,
                                         uint32_t b0, uint32_t b1) {
    asm volatile("mma.sync.aligned.m16n8k16.row.col.f32.f16.f16.f32 "
                 "{%0,%1,%2,%3}, {%4,%5,%6,%7}, {%8,%9}, {%0,%1,%2,%3};"
                 : "+f"(d[0]), "+f"(d[1]), "+f"(d[2]), "+f"(d[3])
                 : "r"(a[0]), "r"(a[1]), "r"(a[2]), "r"(a[3]), "r"(b0), "r"(b1));
}

// ---------------------------------------------------------------------------
// Kernel 1: x fp32 -> fp16 A fragments.
// Entry (c, mt, ks, l, j): m = mt*16 + l/4 + 8*(j&1),
//                          k = c*64 + ks*16 + 2*(l&3) + 8*(j>>1)   (always even)
// value = half2( x[m][k], x[m][k+1] )
// ---------------------------------------------------------------------------
__global__ __launch_bounds__(256) void prep_x_kernel(const float* __restrict__ x) {
    int idx = blockIdx.x * 256 + threadIdx.x;     // 524288 total
    int j  = idx & 3;
    int l  = (idx >> 2) & 31;
    int ks = (idx >> 7) & 3;
    int mt = (idx >> 9) & 15;
    int c  = idx >> 13;
    int m = mt * 16 + (l >> 2) + 8 * (j & 1);
    int k = c * 64 + ks * 16 + 2 * (l & 3) + 8 * (j >> 1);
    float2 v = *reinterpret_cast<const float2*>(x + (size_t)m * KF + k);
    g_xa[idx] = h2u(__floats2half2_rn(v.x, v.y));
}

// ---------------------------------------------------------------------------
// Kernel 2: GEMM. 112 CTAs x 256 threads, 1 CTA/SM.
// 8 warps as 4(m) x 2(n); warp tile 64x64; fp32 accum.
// A: direct LDG.128 of fragments from L2-resident g_xa (no smem).
// B: LDG -> dequant -> STS -> ldsm (2-stage smem, R4 path).
// ---------------------------------------------------------------------------
__global__ __launch_bounds__(256, 1)
void gemm_kernel(const int* __restrict__ qk, const float* __restrict__ qs,
                 const float* __restrict__ qzb, const float* __restrict__ bias,
                 float* __restrict__ out) {
    extern __shared__ unsigned char smem[];
    const uint32_t sb = (uint32_t)__cvta_generic_to_shared(smem);
    const int t = threadIdx.x, lane = t & 31, w = t >> 5;
    const int wm = w >> 1, wn = w & 1;
    const int n0 = blockIdx.x * NTILE;

    // ---- B dequant mapping (R4): nq = lane (n quad), kw = w (k row base) ----
    const int nq = lane;
    const int kw = w;
    const uint32_t sts_base = (uint32_t)kw * 256u
                            + ((uint32_t)((nq >> 1) ^ kw) << 4) + (uint32_t)(nq & 1) * 8u;
    const int*   qbase = qk  + n0 + nq * 4;
    const float* sbase = qs  + n0 + nq * 4;
    const float* zbase = qzb + n0 + nq * 4;

    // ---- B ldsm addressing ----
    const int l15 = lane & 15;
    const uint32_t sx = (uint32_t)(lane & 7);
    const uint32_t lq = (uint32_t)(lane >> 4);
    const uint32_t b_row = (uint32_t)l15 * 256u + (uint32_t)wn * 128u;

    // ---- A fragment source: warp wm covers mtiles wm*4 .. wm*4+3 ----
    const uint4* abase4 = reinterpret_cast<const uint4*>(g_xa)
                        + (size_t)(wm * 4) * (4 * 32) + lane;

    float d[4][8][4];
#pragma unroll
    for (int mb = 0; mb < 4; mb++)
#pragma unroll
        for (int nb = 0; nb < 8; nb++)
#pragma unroll
            for (int i = 0; i < 4; i++) d[mb][nb][i] = 0.0f;

    uint4 aF[2][4];                 // double-buffered A fragments (32 regs)
    int4 bq4[4];
    uint32_t s01, s23, z01, z23;

    auto ldg_a = [&](int c, int ks, uint4 (&dst)[4]) {
        const uint4* p = abase4 + ((size_t)c * 16 * 4 + ks) * 32;
        dst[0] = p[0];
        dst[1] = p[128];            // mtile stride = 4*32 uint4
        dst[2] = p[256];
        dst[3] = p[384];
    };

    auto load_scales = [&](int c) {
        int g = c >> 1;
        float4 s4 = *reinterpret_cast<const float4*>(sbase + (size_t)g * NF);
        float4 z4 = *reinterpret_cast<const float4*>(zbase + (size_t)g * NF);
        s01 = h2u(__floats2half2_rn(s4.x, s4.y)); s23 = h2u(__floats2half2_rn(s4.z, s4.w));
        z01 = h2u(__floats2half2_rn(z4.x, z4.y)); z23 = h2u(__floats2half2_rn(z4.z, z4.w));
    };

    auto ldg_b = [&](int c, int h) {           // rows k = kw + 8*(4h + j)
        const int* qp = qbase + (size_t)c * KC * NF + (size_t)(32 * h) * NF;
#pragma unroll
        for (int j = 0; j < 4; j++)
            bq4[j] = *reinterpret_cast<const int4*>(qp + (size_t)(kw + 8 * j) * NF);
    };

    auto store_b = [&](int st, int h) {
        const __half2 h1024 = u2h(0x64006400u);
        uint32_t base = sb + (uint32_t)st * 16384u + sts_base + (uint32_t)h * 8192u;
#pragma unroll
        for (int j = 0; j < 4; j++) {
            uint32_t u01 = ((uint32_t)bq4[j].x | ((uint32_t)bq4[j].y << 16)) | 0x64006400u;
            uint32_t u23 = ((uint32_t)bq4[j].z | ((uint32_t)bq4[j].w << 16)) | 0x64006400u;
            __half2 q01 = __hsub2(u2h(u01), h1024);
            __half2 q23 = __hsub2(u2h(u23), h1024);
            uint32_t w01 = h2u(__hfma2(q01, u2h(s01), u2h(z01)));
            uint32_t w23 = h2u(__hfma2(q23, u2h(s23), u2h(z23)));
            asm volatile("st.shared.v2.b32 [%0], {%1,%2};"
                         :: "r"(base + (uint32_t)j * 2048u), "r"(w01), "r"(w23) : "memory");
        }
    };

    auto compute_ks = [&](const uint4 (&af)[4], int st, int ks) {
        uint32_t bbase = sb + (uint32_t)st * 16384u + b_row;
        uint32_t b[8][2];
#pragma unroll
        for (int p = 0; p < 4; p++)
            ldsm_x4_t(b[2 * p][0], b[2 * p][1], b[2 * p + 1][0], b[2 * p + 1][1],
                      bbase + (uint32_t)ks * 4096u + ((((uint32_t)(2 * p) + lq) ^ sx) << 4));
#pragma unroll
        for (int mb = 0; mb < 4; mb++) {
            const uint32_t* am = reinterpret_cast<const uint32_t*>(&af[mb]);
#pragma unroll
            for (int nb = 0; nb < 8; nb++)
                mma16816(d[mb][nb], am, b[nb][0], b[nb][1]);
        }
    };

    // ---- prologue: chunk 0 B into stage 0; A(0,0) in flight ----
    ldg_a(0, 0, aF[0]);
    load_scales(0);
    ldg_b(0, 0); store_b(0, 0);
    ldg_b(0, 1); store_b(0, 1);
    __syncthreads();

    // ---- main loop ----
    for (int c = 0; c < NITER; c++) {
        int st = c & 1;
        if (c + 1 < NITER) {
            load_scales(c + 1);
            ldg_b(c + 1, 0);
        }
        ldg_a(c, 1, aF[1]);
        compute_ks(aF[0], st, 0);
        ldg_a(c, 2, aF[0]);
        compute_ks(aF[1], st, 1);
        if (c + 1 < NITER) {
            store_b(st ^ 1, 0);
            ldg_b(c + 1, 1);
        }
        ldg_a(c, 3, aF[1]);
        compute_ks(aF[0], st, 2);
        if (c + 1 < NITER) ldg_a(c + 1, 0, aF[0]);
        compute_ks(aF[1], st, 3);
        if (c + 1 < NITER) store_b(st ^ 1, 1);
        __syncthreads();
    }

    // ---- epilogue: accum + bias -> out ----
    const int gr = lane >> 2;
    const int c2 = (lane & 3) * 2;
#pragma unroll
    for (int mb = 0; mb < 4; mb++) {
        int m = wm * 64 + mb * 16 + gr;
#pragma unroll
        for (int nb = 0; nb < 8; nb++) {
            int n = n0 + wn * 64 + nb * 8 + c2;
            float2 bv = *reinterpret_cast<const float2*>(bias + n);
            float2 o0, o1;
            o0.x = d[mb][nb][0] + bv.x; o0.y = d[mb][nb][1] + bv.y;
            o1.x = d[mb][nb][2] + bv.x; o1.y = d[mb][nb][3] + bv.y;
            *reinterpret_cast<float2*>(out + (size_t)m * NF + n)       = o0;
            *reinterpret_cast<float2*>(out + (size_t)(m + 8) * NF + n) = o1;
        }
    }
}

// ---------------------------------------------------------------------------
// kernel_launch
// ---------------------------------------------------------------------------
extern "C" void kernel_launch(void* const* d_in, const int* in_sizes, int n_in,
                              void* d_out, int out_size) {
    const float* x    = (const float*)d_in[0];
    const int*   qk   = (const int*)d_in[1];
    const float* qs   = (const float*)d_in[2];
    const float* qzb  = (const float*)d_in[3];
    const float* bias = (const float*)d_in[4];
    float* out = (float*)d_out;

    cudaFuncSetAttribute(gemm_kernel, cudaFuncAttributeMaxDynamicSharedMemorySize, SM_TOTAL);

    prep_x_kernel<<<2048, 256>>>(x);
    gemm_kernel<<<NCTA, 256, SM_TOTAL>>>(qk, qs, qzb, bias, out);
}

// round 16
// speedup vs baseline: 1.2211x; 1.2211x over previous
#include <cuda_runtime.h>
#include <cuda_fp16.h>
#include <cstdint>
#include <cstddef>

// ---------------------------------------------------------------------------
// Geometry  (R4 skeleton; only change: per-warp ks phase rotation)
// ---------------------------------------------------------------------------
static constexpr int KF = 4096;
static constexpr int NF = 14336;
static constexpr int MROWS = 256;         // batch rows
static constexpr int NTILE = 128;
static constexpr int NCTA = NF / NTILE;   // 112
static constexpr int KC = 64;             // k per stage
static constexpr int NITER = KF / KC;     // 64

// fp16 image of x, pre-swizzled as the A smem tile image:
// 64 tiles (one per 64-k chunk), each 256 rows x 128B = 32KB.
__device__ __align__(128) unsigned char g_xs[64 * 32768];

// SMEM: A 2 x 32768 | B 2 x 16384
static constexpr uint32_t SM_A = 0;
static constexpr uint32_t SM_B = 65536;
static constexpr uint32_t SM_TOTAL = 98304;

// ---------------------------------------------------------------------------
// Helpers
// ---------------------------------------------------------------------------
__device__ __forceinline__ __half2 u2h(uint32_t u) { return *reinterpret_cast<__half2*>(&u); }
__device__ __forceinline__ uint32_t h2u(__half2 h) { return *reinterpret_cast<uint32_t*>(&h); }

__device__ __forceinline__ void ldsm_x4(uint32_t (&r)[4], uint32_t addr) {
    asm volatile("ldmatrix.sync.aligned.m8n8.x4.shared.b16 {%0,%1,%2,%3}, [%4];"
                 : "=r"(r[0]), "=r"(r[1]), "=r"(r[2]), "=r"(r[3]) : "r"(addr));
}
__device__ __forceinline__ void ldsm_x4_t(uint32_t& r0, uint32_t& r1, uint32_t& r2, uint32_t& r3,
                                          uint32_t addr) {
    asm volatile("ldmatrix.sync.aligned.m8n8.x4.trans.shared.b16 {%0,%1,%2,%3}, [%4];"
                 : "=r"(r0), "=r"(r1), "=r"(r2), "=r"(r3) : "r"(addr));
}
__device__ __forceinline__ void mma16816(float (&d)[4], const uint32_t (&a)[4],
                                         uint32_t b0, uint32_t b1) {
    asm volatile("mma.sync.aligned.m16n8k16.row.col.f32.f16.f16.f32 "
                 "{%0,%1,%2,%3}, {%4,%5,%6,%7}, {%8,%9}, {%0,%1,%2,%3};"
                 : "+f"(d[0]), "+f"(d[1]), "+f"(d[2]), "+f"(d[3])
                 : "r"(a[0]), "r"(a[1]), "r"(a[2]), "r"(a[3]), "r"(b0), "r"(b1));
}

// ---------------------------------------------------------------------------
// Kernel 1: x fp32 -> fp16 pre-swizzled A tile images. 8 k per thread.
// byte(m, kl) = m*128 + (((kl>>3)^(m&7))<<4) + (kl&7)*2
// ---------------------------------------------------------------------------
__global__ __launch_bounds__(256) void prep_x_kernel(const float* __restrict__ x) {
    int idx = blockIdx.x * 256 + threadIdx.x;
    int m   = idx >> 9;
    int kl8 = (idx & 511) * 8;
    const float* xp = x + (size_t)m * KF + kl8;
    float4 v0 = *reinterpret_cast<const float4*>(xp);
    float4 v1 = *reinterpret_cast<const float4*>(xp + 4);
    uint4 o;
    o.x = h2u(__floats2half2_rn(v0.x, v0.y));
    o.y = h2u(__floats2half2_rn(v0.z, v0.w));
    o.z = h2u(__floats2half2_rn(v1.x, v1.y));
    o.w = h2u(__floats2half2_rn(v1.z, v1.w));
    int c = kl8 >> 6, kl = kl8 & 63;
    uint32_t off = (uint32_t)m * 128u + ((((uint32_t)(kl >> 3)) ^ (uint32_t)(m & 7)) << 4);
    *reinterpret_cast<uint4*>(g_xs + (size_t)c * 32768 + off) = o;
}

// ---------------------------------------------------------------------------
// Kernel 2: GEMM. 112 CTAs x 256 threads, 1 CTA/SM.  (R4 structure)
// 8 warps as 4(m) x 2(n); warp tile 64x64; fp32 accum.
// NEW: per-warp ks phase rotation decorrelates ldsm and HMMA bursts
// across the 2 warps sharing each SMSP (and across SMSPs).
// ---------------------------------------------------------------------------
__global__ __launch_bounds__(256, 1)
void gemm_kernel(const int* __restrict__ qk, const float* __restrict__ qs,
                 const float* __restrict__ qzb, const float* __restrict__ bias,
                 float* __restrict__ out) {
    extern __shared__ unsigned char smem[];
    const uint32_t sb = (uint32_t)__cvta_generic_to_shared(smem);
    const int t = threadIdx.x, lane = t & 31, w = t >> 5;
    const int wm = w >> 1, wn = w & 1;
    const int n0 = blockIdx.x * NTILE;
    const int phase = w & 3;                  // ks rotation per warp

    // ---- dequant mapping ----
    const int nq = lane;
    const int kw = w;
    const uint32_t sts_base = (uint32_t)kw * 256u
                            + ((uint32_t)((nq >> 1) ^ kw) << 4) + (uint32_t)(nq & 1) * 8u;
    const int*   qbase = qk  + n0 + nq * 4;
    const float* sbase = qs  + n0 + nq * 4;
    const float* zbase = qzb + n0 + nq * 4;

    // ---- ldmatrix addressing ----
    const int l15 = lane & 15;
    const uint32_t sx = (uint32_t)(lane & 7);
    const uint32_t lq = (uint32_t)(lane >> 4);
    uint32_t a_row[4];
#pragma unroll
    for (int mb = 0; mb < 4; mb++)
        a_row[mb] = (uint32_t)(wm * 64 + mb * 16 + l15) * 128u;
    const uint32_t b_row = (uint32_t)l15 * 256u + (uint32_t)wn * 128u;

    float d[4][8][4];
#pragma unroll
    for (int mb = 0; mb < 4; mb++)
#pragma unroll
        for (int nb = 0; nb < 8; nb++)
#pragma unroll
            for (int i = 0; i < 4; i++) d[mb][nb][i] = 0.0f;

    int4 bq4[4];
    uint32_t s01, s23, z01, z23;

    auto prefetch_a = [&](int c, int st) {
        const unsigned char* asrc = g_xs + (size_t)c * 32768 + (size_t)t * 16;
        uint32_t adst = sb + SM_A + (uint32_t)st * 32768u + (uint32_t)t * 16u;
#pragma unroll
        for (int i = 0; i < 8; i++) {
            asm volatile("cp.async.cg.shared.global [%0], [%1], 16;"
                         :: "r"(adst + (uint32_t)i * 4096u), "l"(asrc + (size_t)i * 4096)
                         : "memory");
        }
        asm volatile("cp.async.commit_group;" ::: "memory");
    };

    auto load_scales = [&](int c) {
        int g = c >> 1;
        float4 s4 = *reinterpret_cast<const float4*>(sbase + (size_t)g * NF);
        float4 z4 = *reinterpret_cast<const float4*>(zbase + (size_t)g * NF);
        s01 = h2u(__floats2half2_rn(s4.x, s4.y)); s23 = h2u(__floats2half2_rn(s4.z, s4.w));
        z01 = h2u(__floats2half2_rn(z4.x, z4.y)); z23 = h2u(__floats2half2_rn(z4.z, z4.w));
    };

    auto ldg_b = [&](int c, int h) {           // rows k = kw + 8*(4h + j)
        const int* qp = qbase + (size_t)c * KC * NF + (size_t)(32 * h) * NF;
#pragma unroll
        for (int j = 0; j < 4; j++)
            bq4[j] = *reinterpret_cast<const int4*>(qp + (size_t)(kw + 8 * j) * NF);
    };

    auto store_b = [&](int st, int h) {
        const __half2 h1024 = u2h(0x64006400u);
        uint32_t base = sb + SM_B + (uint32_t)st * 16384u + sts_base + (uint32_t)h * 8192u;
#pragma unroll
        for (int j = 0; j < 4; j++) {
            uint32_t u01 = ((uint32_t)bq4[j].x | ((uint32_t)bq4[j].y << 16)) | 0x64006400u;
            uint32_t u23 = ((uint32_t)bq4[j].z | ((uint32_t)bq4[j].w << 16)) | 0x64006400u;
            __half2 q01 = __hsub2(u2h(u01), h1024);
            __half2 q23 = __hsub2(u2h(u23), h1024);
            uint32_t w01 = h2u(__hfma2(q01, u2h(s01), u2h(z01)));
            uint32_t w23 = h2u(__hfma2(q23, u2h(s23), u2h(z23)));
            asm volatile("st.shared.v2.b32 [%0], {%1,%2};"
                         :: "r"(base + (uint32_t)j * 2048u), "r"(w01), "r"(w23) : "memory");
        }
    };

    // One ks step (4 A ldsm + 4 B ldsm + 32 HMMA)
    auto compute_one = [&](int st, int ks) {
        uint32_t abase = sb + SM_A + (uint32_t)st * 32768u;
        uint32_t bbase = sb + SM_B + (uint32_t)st * 16384u + b_row;
        uint32_t a[4][4];
#pragma unroll
        for (int mb = 0; mb < 4; mb++)
            ldsm_x4(a[mb], abase + a_row[mb] + ((((uint32_t)(2 * ks) + lq) ^ sx) << 4));
        uint32_t b[8][2];
#pragma unroll
        for (int p = 0; p < 4; p++)
            ldsm_x4_t(b[2 * p][0], b[2 * p][1], b[2 * p + 1][0], b[2 * p + 1][1],
                      bbase + (uint32_t)ks * 4096u + ((((uint32_t)(2 * p) + lq) ^ sx) << 4));
#pragma unroll
        for (int mb = 0; mb < 4; mb++)
#pragma unroll
            for (int nb = 0; nb < 8; nb++)
                mma16816(d[mb][nb], a[mb], b[nb][0], b[nb][1]);
    };

    // ---- prologue: chunk 0 into stage 0 ----
    prefetch_a(0, 0);
    load_scales(0);
    ldg_b(0, 0); store_b(0, 0);
    ldg_b(0, 1); store_b(0, 1);
    asm volatile("cp.async.wait_group 0;" ::: "memory");
    __syncthreads();

    // ---- main loop (R4 skeleton, ks order rotated per warp) ----
    for (int c = 0; c < NITER; c++) {
        int st = c & 1;
        if (c + 1 < NITER) {
            prefetch_a(c + 1, st ^ 1);
            load_scales(c + 1);
            ldg_b(c + 1, 0);
        }
        compute_one(st, phase);
        compute_one(st, (phase + 1) & 3);
        if (c + 1 < NITER) {
            store_b(st ^ 1, 0);
            ldg_b(c + 1, 1);
        }
        compute_one(st, (phase + 2) & 3);
        compute_one(st, (phase + 3) & 3);
        if (c + 1 < NITER) {
            store_b(st ^ 1, 1);
            asm volatile("cp.async.wait_group 0;" ::: "memory");
        }
        __syncthreads();
    }

    // ---- epilogue: accum + bias -> out ----
    const int gr = lane >> 2;
    const int c2 = (lane & 3) * 2;
#pragma unroll
    for (int mb = 0; mb < 4; mb++) {
        int m = wm * 64 + mb * 16 + gr;
#pragma unroll
        for (int nb = 0; nb < 8; nb++) {
            int n = n0 + wn * 64 + nb * 8 + c2;
            float2 bv = *reinterpret_cast<const float2*>(bias + n);
            float2 o0, o1;
            o0.x = d[mb][nb][0] + bv.x; o0.y = d[mb][nb][1] + bv.y;
            o1.x = d[mb][nb][2] + bv.x; o1.y = d[mb][nb][3] + bv.y;
            *reinterpret_cast<float2*>(out + (size_t)m * NF + n)       = o0;
            *reinterpret_cast<float2*>(out + (size_t)(m + 8) * NF + n) = o1;
        }
    }
}

// ---------------------------------------------------------------------------
// kernel_launch
// ---------------------------------------------------------------------------
extern "C" void kernel_launch(void* const* d_in, const int* in_sizes, int n_in,
                              void* d_out, int out_size) {
    const float* x    = (const float*)d_in[0];
    const int*   qk   = (const int*)d_in[1];
    const float* qs   = (const float*)d_in[2];
    const float* qzb  = (const float*)d_in[3];
    const float* bias = (const float*)d_in[4];
    float* out = (float*)d_out;

    cudaFuncSetAttribute(gemm_kernel, cudaFuncAttributeMaxDynamicSharedMemorySize, SM_TOTAL);

    prep_x_kernel<<<512, 256>>>(x);
    gemm_kernel<<<NCTA, 256, SM_TOTAL>>>(qk, qs, qzb, bias, out);
}